// round 16
// baseline (speedup 1.0000x reference)
#include <cuda_runtime.h>
#include <math.h>

typedef unsigned long long u64;

__device__ __forceinline__ void upk2(u64 v, float& lo, float& hi) {
    asm("mov.b64 {%0, %1}, %2;" : "=f"(lo), "=f"(hi) : "l"(v));
}
__device__ __forceinline__ u64 pk2(float lo, float hi) {
    u64 r; asm("mov.b64 %0, {%1, %2};" : "=l"(r) : "f"(lo), "f"(hi)); return r;
}
__device__ __forceinline__ u64 fma2(u64 a, u64 b, u64 c) {
    u64 d; asm("fma.rn.f32x2 %0, %1, %2, %3;" : "=l"(d) : "l"(a), "l"(b), "l"(c)); return d;
}
__device__ __forceinline__ u64 add2(u64 a, u64 b) {
    u64 d; asm("add.rn.f32x2 %0, %1, %2;" : "=l"(d) : "l"(a), "l"(b)); return d;
}
__device__ __forceinline__ unsigned int f16x2_of(u64 t) {
    float lo, hi; upk2(t, lo, hi);
    unsigned int r;
    asm("cvt.rn.f16x2.f32 %0, %1, %2;" : "=r"(r) : "f"(hi), "f"(lo));
    return r;
}
__device__ __forceinline__ unsigned int hex2(unsigned int x) {
    unsigned int r; asm("ex2.approx.f16x2 %0, %1;" : "=r"(r) : "r"(x)); return r;
}
__device__ __forceinline__ unsigned int hadd2(unsigned int a, unsigned int b) {
    unsigned int r; asm("add.rn.f16x2 %0, %1, %2;" : "=r"(r) : "r"(a), "r"(b)); return r;
}
__device__ __forceinline__ void h2_to_f32(unsigned int v, float& lo, float& hi) {
    asm("{\n\t"
        ".reg .b16 l, h;\n\t"
        "mov.b32 {l, h}, %2;\n\t"
        "cvt.f32.f16 %0, l;\n\t"
        "cvt.f32.f16 %1, h;\n\t"
        "}" : "=f"(lo), "=f"(hi) : "r"(v));
}

#define MAGIC_F 12582912.0f   // 1.5 * 2^23

// Packed deg-3 polynomial exp2 accumulate (zero XU-pipe cost).
// 2^f ~= 1 + f*(C1 + f*(C2 + f*C3)), f in [-0.5, 0.5];
// acc += 2^n * (1 + f*q)  via u = fma2(s, r, s). R8-validated rounding and
// exponent-insert construction.
__device__ __forceinline__ void poly_acc(u64 t, u64 MG, u64 NMG, u64 NONE,
                                         u64 C1p, u64 C2p, u64 C3p, u64& accP) {
    float d0, d1;
    upk2(t, d0, d1);
    d0 = fmaxf(d0, -125.0f);            // underflow clamp (alu FMNMX)
    d1 = fmaxf(d1, -125.0f);
    u64 tdc = pk2(d0, d1);
    u64 k2 = add2(tdc, MG);             // round-to-nearest in mantissa
    u64 n2 = add2(k2, NMG);             // n = rint(t)
    u64 f2 = fma2(NONE, n2, tdc);       // f = t - n in [-0.5, 0.5]
    u64 q  = fma2(C3p, f2, C2p);
    q      = fma2(q,   f2, C1p);
    u64 r  = fma2(q,   f2, 0ull);       // r = f*q
    float kf0, kf1;
    upk2(k2, kf0, kf1);
    int s0b = (__float_as_int(kf0) << 23) + 0x3F800000;  // 2^n bits
    int s1b = (__float_as_int(kf1) << 23) + 0x3F800000;
    u64 s2 = pk2(__int_as_float(s0b), __int_as_float(s1b));
    u64 u  = fma2(s2, r, s2);           // s*(1 + f*q)
    accP = add2(accP, u);
}

// grid = (M/64, B), 128 threads = 4 K-quarters x 32 lanes.
// Each lane owns TWO points (m0, m1=m0+32). Per outer iter: 16 samples.
// Point A: all pairs via fp16x2 MUFU ex2. Point B: 3/4 pairs fp16x2 + 1/4
// via fp32x2 polynomial (XU-free). fp16 trees flushed once per 16 samples.
__global__ __launch_bounds__(128)
void kde_main_kernel(const float* __restrict__ inputs,
                     const float* __restrict__ pts,
                     float* __restrict__ out,
                     int N, int M, float gamma2, float scale_out) {
    const int b = blockIdx.y;
    const int lane = threadIdx.x & 31;
    const int quad = threadIdx.x >> 5;           // 0..3
    const int m0 = blockIdx.x * 64 + lane;
    const int m1 = m0 + 32;
    const int Nc = N >> 2;                       // samples per quarter

    __shared__ __align__(16) float sxx[2048];
    __shared__ __align__(16) float sxy[2048];
    __shared__ __align__(16) float ssn[2048];
    __shared__ float spart[3][64];

    // Stage + preprocess all N samples: (N,2) -> pair-packed SoA
    {
        const float4* src = (const float4*)(inputs + (size_t)b * N * 2);
        u64* dxx = (u64*)sxx;
        u64* dxy = (u64*)sxy;
        u64* dsn = (u64*)ssn;
        const int nv = N >> 1;                   // float4s, 2 samples each
        for (int j = threadIdx.x; j < nv; j += 128) {
            float4 v = src[j];
            float s0 = -gamma2 * fmaf(v.x, v.x, v.y * v.y);
            float s1 = -gamma2 * fmaf(v.z, v.z, v.w * v.w);
            dxx[j] = pk2(v.x, v.z);
            dxy[j] = pk2(v.y, v.w);
            dsn[j] = pk2(s0, s1);
        }
    }

    // Point constants (log2 units)
    const float pxA = pts[2 * m0], pyA = pts[2 * m0 + 1];
    const float pxB = pts[2 * m1], pyB = pts[2 * m1 + 1];
    const float qxA = 2.0f * gamma2 * pxA, qyA = 2.0f * gamma2 * pyA;
    const float qxB = 2.0f * gamma2 * pxB, qyB = 2.0f * gamma2 * pyB;
    const float amA = -gamma2 * fmaf(pxA, pxA, pyA * pyA);
    const float amB = -gamma2 * fmaf(pxB, pxB, pyB * pyB);

    __syncthreads();

    const u64 qxA2 = pk2(qxA, qxA), qyA2 = pk2(qyA, qyA), amA2 = pk2(amA, amA);
    const u64 qxB2 = pk2(qxB, qxB), qyB2 = pk2(qyB, qyB), amB2 = pk2(amB, amB);

    // Poly constants (uniform, expect UR promotion)
    const u64 MG   = pk2(MAGIC_F, MAGIC_F);
    const u64 NMG  = pk2(-MAGIC_F, -MAGIC_F);
    const u64 NONE = pk2(-1.0f, -1.0f);
    const u64 C1p  = pk2(0.69314718f, 0.69314718f);
    const u64 C2p  = pk2(0.24022650f, 0.24022650f);
    const u64 C3p  = pk2(0.05550411f, 0.05550411f);

    // This quarter's chunk: samples [quad*Nc, (quad+1)*Nc)
    const int base = quad * (Nc >> 2);           // ulonglong2 index offset
    const ulonglong2* hx = (const ulonglong2*)sxx + base;
    const ulonglong2* hy = (const ulonglong2*)sxy + base;
    const ulonglong2* hs = (const ulonglong2*)ssn + base;

    float a0 = 0.f, a1 = 0.f, b0 = 0.f, b1 = 0.f;
    u64 accP = 0ull;

    const int nouter = Nc >> 4;                  // 16 samples per outer iter

    #pragma unroll 1
    for (int qq = 0; qq < nouter; qq++) {
        unsigned int wA[2], wB[2];
        #pragma unroll
        for (int s = 0; s < 2; s++) {
            int j = 4 * qq + 2 * s;
            ulonglong2 X0 = hx[j], X1 = hx[j + 1];
            ulonglong2 Y0 = hy[j], Y1 = hy[j + 1];
            ulonglong2 S0 = hs[j], S1 = hs[j + 1];

            // point A: 4 pairs, all fp16x2-MUFU
            u64 t1 = fma2(qxA2, X0.x, S0.x); t1 = fma2(qyA2, Y0.x, t1); t1 = add2(t1, amA2);
            u64 t2 = fma2(qxA2, X0.y, S0.y); t2 = fma2(qyA2, Y0.y, t2); t2 = add2(t2, amA2);
            u64 t3 = fma2(qxA2, X1.x, S1.x); t3 = fma2(qyA2, Y1.x, t3); t3 = add2(t3, amA2);
            u64 t4 = fma2(qxA2, X1.y, S1.y); t4 = fma2(qyA2, Y1.y, t4); t4 = add2(t4, amA2);
            unsigned int e1 = hex2(f16x2_of(t1));
            unsigned int e2 = hex2(f16x2_of(t2));
            unsigned int e3 = hex2(f16x2_of(t3));
            unsigned int e4 = hex2(f16x2_of(t4));
            wA[s] = hadd2(hadd2(e1, e2), hadd2(e3, e4));

            // point B: 3 pairs fp16x2 + 1 pair poly (XU-free)
            u64 u1 = fma2(qxB2, X0.x, S0.x); u1 = fma2(qyB2, Y0.x, u1); u1 = add2(u1, amB2);
            u64 u2 = fma2(qxB2, X0.y, S0.y); u2 = fma2(qyB2, Y0.y, u2); u2 = add2(u2, amB2);
            u64 u3 = fma2(qxB2, X1.x, S1.x); u3 = fma2(qyB2, Y1.x, u3); u3 = add2(u3, amB2);
            u64 u4 = fma2(qxB2, X1.y, S1.y); u4 = fma2(qyB2, Y1.y, u4); u4 = add2(u4, amB2);
            unsigned int f1 = hex2(f16x2_of(u1));
            unsigned int f2_ = hex2(f16x2_of(u2));
            unsigned int f3 = hex2(f16x2_of(u3));
            wB[s] = hadd2(hadd2(f1, f2_), f3);

            poly_acc(u4, MG, NMG, NONE, C1p, C2p, C3p, accP);
        }

        // flush once per 16 samples (fp16 sums <= 8, safe)
        float lo, hi;
        h2_to_f32(hadd2(wA[0], wA[1]), lo, hi);
        a0 += lo; a1 += hi;
        h2_to_f32(hadd2(wB[0], wB[1]), lo, hi);
        b0 += lo; b1 += hi;
    }

    float p0, p1;
    upk2(accP, p0, p1);
    float totA = (a0 + a1) * scale_out;
    float totB = ((b0 + b1) + (p0 + p1)) * scale_out;

    // Combine quarters: quads 1-3 publish, quad 0 reduces in fixed order.
    if (quad != 0) {
        spart[quad - 1][lane]      = totA;
        spart[quad - 1][lane + 32] = totB;
    }
    __syncthreads();
    if (quad == 0) {
        float sA = totA + spart[0][lane]      + spart[1][lane]      + spart[2][lane];
        float sB = totB + spart[0][lane + 32] + spart[1][lane + 32] + spart[2][lane + 32];
        const size_t bm = (size_t)b * M;
        out[bm + m0] = sA;
        out[bm + m1] = sB;
    }
}

extern "C" void kernel_launch(void* const* d_in, const int* in_sizes, int n_in,
                              void* d_out, int out_size) {
    const float* inputs = (const float*)d_in[0];   // (B, N, 2) float32
    const float* pts    = (const float*)d_in[1];   // (M, 2) float32
    float* out          = (float*)d_out;           // (B, M) float32

    const int d = 2;
    const int M  = in_sizes[1] / d;                // 512
    const int BN = in_sizes[0] / d;                // B*N
    const int B  = out_size / M;                   // 128
    const int N  = BN / B;                         // 2048

    // Silverman bandwidth (d=2)
    double h = pow(4.0 / (d + 2), 1.0 / (d + 4)) * pow((double)N, -1.0 / (d + 4));
    double coef = 1.0 / pow(2.0 * M_PI * h * h, d / 2.0);
    double gamma = 0.5 / (h * h);
    float gamma2 = (float)(gamma * 1.4426950408889634);  // fold 1/ln2 for ex2
    float scale_out = (float)(coef / (double)N);

    dim3 grid(M / 64, B);   // (8, 128) = 1024 blocks, 128 threads
    kde_main_kernel<<<grid, 128>>>(inputs, pts, out, N, M, gamma2, scale_out);
}

// round 17
// speedup vs baseline: 1.1011x; 1.1011x over previous
#include <cuda_runtime.h>
#include <math.h>

typedef unsigned long long u64;

__device__ __forceinline__ void upk2(u64 v, float& lo, float& hi) {
    asm("mov.b64 {%0, %1}, %2;" : "=f"(lo), "=f"(hi) : "l"(v));
}
__device__ __forceinline__ u64 pk2(float lo, float hi) {
    u64 r; asm("mov.b64 %0, {%1, %2};" : "=l"(r) : "f"(lo), "f"(hi)); return r;
}
__device__ __forceinline__ u64 fma2(u64 a, u64 b, u64 c) {
    u64 d; asm("fma.rn.f32x2 %0, %1, %2, %3;" : "=l"(d) : "l"(a), "l"(b), "l"(c)); return d;
}
__device__ __forceinline__ u64 add2(u64 a, u64 b) {
    u64 d; asm("add.rn.f32x2 %0, %1, %2;" : "=l"(d) : "l"(a), "l"(b)); return d;
}
__device__ __forceinline__ unsigned int f16x2_of(u64 t) {
    float lo, hi; upk2(t, lo, hi);
    unsigned int r;
    asm("cvt.rn.f16x2.f32 %0, %1, %2;" : "=r"(r) : "f"(hi), "f"(lo));
    return r;
}
__device__ __forceinline__ unsigned int hex2(unsigned int x) {
    unsigned int r; asm("ex2.approx.f16x2 %0, %1;" : "=r"(r) : "r"(x)); return r;
}
__device__ __forceinline__ unsigned int hadd2(unsigned int a, unsigned int b) {
    unsigned int r; asm("add.rn.f16x2 %0, %1, %2;" : "=r"(r) : "r"(a), "r"(b)); return r;
}
__device__ __forceinline__ void h2_to_f32(unsigned int v, float& lo, float& hi) {
    asm("{\n\t"
        ".reg .b16 l, h;\n\t"
        "mov.b32 {l, h}, %2;\n\t"
        "cvt.f32.f16 %0, l;\n\t"
        "cvt.f32.f16 %1, h;\n\t"
        "}" : "=f"(lo), "=f"(hi) : "r"(v));
}

// grid = (M/64, B), 128 threads = 4 K-quarters x 32 lanes.
// Each lane owns TWO points (m0, m1 = m0+32); each quarter covers N/4
// samples. Outer iter = 16 samples (32 evals): two sub-iters build fp16
// trees (carried in wA/wB), single fp32 flush per point per outer iter.
// All exponentials via fp16x2 MUFU ex2 (NO polynomial path).
// t = am2 + qx*xx + qy*xy + sn <= 0 always -> exp2 in [0,1], fp16-safe;
// tree partial sums <= 8, fp16-safe.
__global__ __launch_bounds__(128)
void kde_main_kernel(const float* __restrict__ inputs,
                     const float* __restrict__ pts,
                     float* __restrict__ out,
                     int N, int M, float gamma2, float scale_out) {
    const int b = blockIdx.y;
    const int lane = threadIdx.x & 31;
    const int quad = threadIdx.x >> 5;           // 0..3
    const int m0 = blockIdx.x * 64 + lane;
    const int m1 = m0 + 32;
    const int Nc = N >> 2;                       // samples per quarter

    __shared__ __align__(16) float sxx[2048];
    __shared__ __align__(16) float sxy[2048];
    __shared__ __align__(16) float ssn[2048];
    __shared__ float spart[3][64];

    // Stage + preprocess all N samples: (N,2) -> pair-packed SoA
    {
        const float4* src = (const float4*)(inputs + (size_t)b * N * 2);
        u64* dxx = (u64*)sxx;
        u64* dxy = (u64*)sxy;
        u64* dsn = (u64*)ssn;
        const int nv = N >> 1;                   // float4s, 2 samples each
        for (int j = threadIdx.x; j < nv; j += 128) {
            float4 v = src[j];
            float s0 = -gamma2 * fmaf(v.x, v.x, v.y * v.y);
            float s1 = -gamma2 * fmaf(v.z, v.z, v.w * v.w);
            dxx[j] = pk2(v.x, v.z);
            dxy[j] = pk2(v.y, v.w);
            dsn[j] = pk2(s0, s1);
        }
    }

    // Point constants (log2 units)
    const float pxA = pts[2 * m0], pyA = pts[2 * m0 + 1];
    const float pxB = pts[2 * m1], pyB = pts[2 * m1 + 1];
    const float qxA = 2.0f * gamma2 * pxA, qyA = 2.0f * gamma2 * pyA;
    const float qxB = 2.0f * gamma2 * pxB, qyB = 2.0f * gamma2 * pyB;
    const float amA = -gamma2 * fmaf(pxA, pxA, pyA * pyA);
    const float amB = -gamma2 * fmaf(pxB, pxB, pyB * pyB);

    __syncthreads();

    const u64 qxA2 = pk2(qxA, qxA), qyA2 = pk2(qyA, qyA), amA2 = pk2(amA, amA);
    const u64 qxB2 = pk2(qxB, qxB), qyB2 = pk2(qyB, qyB), amB2 = pk2(amB, amB);

    // This quarter's chunk: samples [quad*Nc, (quad+1)*Nc)
    const int base = quad * (Nc >> 2);           // ulonglong2 index offset
    const ulonglong2* hx = (const ulonglong2*)sxx + base;
    const ulonglong2* hy = (const ulonglong2*)sxy + base;
    const ulonglong2* hs = (const ulonglong2*)ssn + base;

    float a0 = 0.f, a1 = 0.f, b0 = 0.f, b1 = 0.f;

    const int nouter = Nc >> 4;                  // 16 samples per outer iter

    #pragma unroll 1
    for (int qq = 0; qq < nouter; qq++) {
        unsigned int wA[2], wB[2];
        #pragma unroll
        for (int s = 0; s < 2; s++) {
            int j = 4 * qq + 2 * s;
            ulonglong2 X0 = hx[j], X1 = hx[j + 1];
            ulonglong2 Y0 = hy[j], Y1 = hy[j + 1];
            ulonglong2 S0 = hs[j], S1 = hs[j + 1];

            // point A: 4 pairs, fp16x2-MUFU
            u64 t1 = fma2(qxA2, X0.x, S0.x); t1 = fma2(qyA2, Y0.x, t1); t1 = add2(t1, amA2);
            u64 t2 = fma2(qxA2, X0.y, S0.y); t2 = fma2(qyA2, Y0.y, t2); t2 = add2(t2, amA2);
            u64 t3 = fma2(qxA2, X1.x, S1.x); t3 = fma2(qyA2, Y1.x, t3); t3 = add2(t3, amA2);
            u64 t4 = fma2(qxA2, X1.y, S1.y); t4 = fma2(qyA2, Y1.y, t4); t4 = add2(t4, amA2);
            unsigned int e1 = hex2(f16x2_of(t1));
            unsigned int e2 = hex2(f16x2_of(t2));
            unsigned int e3 = hex2(f16x2_of(t3));
            unsigned int e4 = hex2(f16x2_of(t4));
            wA[s] = hadd2(hadd2(e1, e2), hadd2(e3, e4));

            // point B: 4 pairs, fp16x2-MUFU
            u64 u1 = fma2(qxB2, X0.x, S0.x); u1 = fma2(qyB2, Y0.x, u1); u1 = add2(u1, amB2);
            u64 u2 = fma2(qxB2, X0.y, S0.y); u2 = fma2(qyB2, Y0.y, u2); u2 = add2(u2, amB2);
            u64 u3 = fma2(qxB2, X1.x, S1.x); u3 = fma2(qyB2, Y1.x, u3); u3 = add2(u3, amB2);
            u64 u4 = fma2(qxB2, X1.y, S1.y); u4 = fma2(qyB2, Y1.y, u4); u4 = add2(u4, amB2);
            unsigned int f1 = hex2(f16x2_of(u1));
            unsigned int f2 = hex2(f16x2_of(u2));
            unsigned int f3 = hex2(f16x2_of(u3));
            unsigned int f4 = hex2(f16x2_of(u4));
            wB[s] = hadd2(hadd2(f1, f2), hadd2(f3, f4));
        }

        // single fp32 flush per point per 16 samples (fp16 sums <= 8)
        float lo, hi;
        h2_to_f32(hadd2(wA[0], wA[1]), lo, hi);
        a0 += lo; a1 += hi;
        h2_to_f32(hadd2(wB[0], wB[1]), lo, hi);
        b0 += lo; b1 += hi;
    }

    float totA = (a0 + a1) * scale_out;
    float totB = (b0 + b1) * scale_out;

    // Combine quarters: quads 1-3 publish, quad 0 reduces in fixed order.
    if (quad != 0) {
        spart[quad - 1][lane]      = totA;
        spart[quad - 1][lane + 32] = totB;
    }
    __syncthreads();
    if (quad == 0) {
        float sA = totA + spart[0][lane]      + spart[1][lane]      + spart[2][lane];
        float sB = totB + spart[0][lane + 32] + spart[1][lane + 32] + spart[2][lane + 32];
        const size_t bm = (size_t)b * M;
        out[bm + m0] = sA;
        out[bm + m1] = sB;
    }
}

extern "C" void kernel_launch(void* const* d_in, const int* in_sizes, int n_in,
                              void* d_out, int out_size) {
    const float* inputs = (const float*)d_in[0];   // (B, N, 2) float32
    const float* pts    = (const float*)d_in[1];   // (M, 2) float32
    float* out          = (float*)d_out;           // (B, M) float32

    const int d = 2;
    const int M  = in_sizes[1] / d;                // 512
    const int BN = in_sizes[0] / d;                // B*N
    const int B  = out_size / M;                   // 128
    const int N  = BN / B;                         // 2048

    // Silverman bandwidth (d=2)
    double h = pow(4.0 / (d + 2), 1.0 / (d + 4)) * pow((double)N, -1.0 / (d + 4));
    double coef = 1.0 / pow(2.0 * M_PI * h * h, d / 2.0);
    double gamma = 0.5 / (h * h);
    float gamma2 = (float)(gamma * 1.4426950408889634);  // fold 1/ln2 for ex2
    float scale_out = (float)(coef / (double)N);

    dim3 grid(M / 64, B);   // (8, 128) = 1024 blocks, 128 threads
    kde_main_kernel<<<grid, 128>>>(inputs, pts, out, N, M, gamma2, scale_out);
}